// round 6
// baseline (speedup 1.0000x reference)
#include <cuda_runtime.h>

// Problem constants
#define NPTS    131072
#define DIM     128
#define NBOOK   4
#define KCODES  1024
#define NCODES  4096

#define THREADS 256
#define SMEM_MAIN (2 * 65536)

__device__ float g_csq[NCODES];

// 16-byte-granular swizzle: XOR byte-address bits [6:4] with (row>>3)&7.
// Same function for store and load -> self-consistent.
__device__ __forceinline__ unsigned swz(unsigned row, unsigned kb) {
    return row * 512u + (kb ^ (((row >> 3) & 7u) << 4));
}

// (val, idx) argmin with lowest-index tie-break (matches jnp.argmin).
__device__ __forceinline__ void amin2(float& v, int& i, float ov, int oi) {
    if (ov < v || (ov == v && oi < i)) { v = ov; i = oi; }
}

// ||c||^2 for all 4096 codes. One warp per code.
__global__ void csq_kernel(const float* __restrict__ cb) {
    int warp = threadIdx.x >> 5;
    int lane = threadIdx.x & 31;
    int code = blockIdx.x * 8 + warp;
    float4 v = reinterpret_cast<const float4*>(cb)[code * 32 + lane];
    float s = v.x * v.x + v.y * v.y + v.z * v.z + v.w * v.w;
#pragma unroll
    for (int o = 16; o > 0; o >>= 1) s += __shfl_xor_sync(0xffffffffu, s, o);
    if (lane == 0) g_csq[code] = s;
}

extern __shared__ char smem[];

__global__ void __launch_bounds__(THREADS, 1)
rqk_kernel(const float* __restrict__ x, const float* __restrict__ cb,
           float* __restrict__ out) {
    char* xs = smem;
    char* cs = smem + 65536;

    const int tid  = threadIdx.x;
    const int lane = tid & 31;
    const int warp = tid >> 5;
    const int tx   = lane & 15;               // code group (8 codes)
    const int ty   = warp * 2 + (lane >> 4);  // row group (8 rows), 0..15
    const int row0 = blockIdx.x * 128;

    // ---- load x tile [128 x 128] ----
    {
        const float4* x4 = reinterpret_cast<const float4*>(x) + (size_t)row0 * 32;
#pragma unroll
        for (int it = 0; it < 16; ++it) {
            int idx = it * 256 + tid;
            int r = idx >> 5, c4 = idx & 31;
            *reinterpret_cast<float4*>(xs + swz(r, c4 * 16)) = x4[r * 32 + c4];
        }
    }

    const float4* cb4 = reinterpret_cast<const float4*>(cb);
    float best_v[8];
    int   best_i[8];

    for (int t = 0; t < 32; ++t) {
        __syncthreads();
        // ---- load code tile [128 x 128] ----
#pragma unroll
        for (int it = 0; it < 16; ++it) {
            int idx = it * 256 + tid;
            int r = idx >> 5, c4 = idx & 31;
            *reinterpret_cast<float4*>(cs + swz(r, c4 * 16)) =
                cb4[((size_t)t * 128 + r) * 32 + c4];
        }
        __syncthreads();

        if ((t & 7) == 0) {
#pragma unroll
            for (int i = 0; i < 8; ++i) { best_v[i] = 3.4e38f; best_i[i] = 0; }
        }

        // ---- 8x8 micro-tile dots ----
        float acc[8][8];
#pragma unroll
        for (int i = 0; i < 8; ++i)
#pragma unroll
            for (int j = 0; j < 8; ++j) acc[i][j] = 0.0f;

#pragma unroll 2
        for (int k4 = 0; k4 < 32; ++k4) {
            float4 a[8], b[8];
#pragma unroll
            for (int i = 0; i < 8; ++i)
                a[i] = *reinterpret_cast<const float4*>(xs + swz(ty * 8 + i, k4 * 16));
#pragma unroll
            for (int j = 0; j < 8; ++j)
                b[j] = *reinterpret_cast<const float4*>(cs + swz(tx * 8 + j, k4 * 16));
#pragma unroll
            for (int i = 0; i < 8; ++i)
#pragma unroll
                for (int j = 0; j < 8; ++j) {
                    acc[i][j] = fmaf(a[i].x, b[j].x, acc[i][j]);
                    acc[i][j] = fmaf(a[i].y, b[j].y, acc[i][j]);
                    acc[i][j] = fmaf(a[i].z, b[j].z, acc[i][j]);
                    acc[i][j] = fmaf(a[i].w, b[j].w, acc[i][j]);
                }
        }

        // ---- score = csq - 2*dot, running per-row argmin ----
        float csq_r[8];
#pragma unroll
        for (int j = 0; j < 8; ++j) csq_r[j] = g_csq[t * 128 + tx * 8 + j];

#pragma unroll
        for (int i = 0; i < 8; ++i)
#pragma unroll
            for (int j = 0; j < 8; ++j) {
                float s = fmaf(-2.0f, acc[i][j], csq_r[j]);
                int cid = ((t & 7) << 7) + (tx << 3) + j;
                amin2(best_v[i], best_i[i], s, cid);
            }

        // ---- end of book: argmin across 16 tx-lanes, store as FLOAT ----
        if ((t & 7) == 7) {
#pragma unroll
            for (int i = 0; i < 8; ++i) {
                float v  = best_v[i];
                int   bi = best_i[i];
#pragma unroll
                for (int off = 1; off < 16; off <<= 1) {
                    float ov = __shfl_xor_sync(0xffffffffu, v, off);
                    int   oi = __shfl_xor_sync(0xffffffffu, bi, off);
                    amin2(v, bi, ov, oi);
                }
                if (tx == 0)
                    out[(size_t)(row0 + ty * 8 + i) * NBOOK + (t >> 3)] =
                        (float)bi;   // output dtype is float32 (round 1-5 deduction)
            }
        }
    }
}

extern "C" void kernel_launch(void* const* d_in, const int* in_sizes, int n_in,
                              void* d_out, int out_size) {
    // Identify tensors by exact size (element- or byte-count), any order.
    const float* x  = nullptr;
    const float* cb = nullptr;
    for (int i = 0; i < n_in; ++i) {
        long long s = in_sizes[i];
        if (s == 16777216LL || s == 67108864LL) x  = (const float*)d_in[i];
        if (s == 524288LL   || s == 2097152LL)  cb = (const float*)d_in[i];
    }
    if (!x)  x  = (const float*)d_in[0];
    if (!cb) cb = (const float*)d_in[n_in > 1 ? 1 : 0];

    csq_kernel<<<NCODES / 8, 256>>>(cb);

    cudaFuncSetAttribute(rqk_kernel, cudaFuncAttributeMaxDynamicSharedMemorySize,
                         SMEM_MAIN);
    rqk_kernel<<<NPTS / 128, THREADS, SMEM_MAIN>>>(x, cb, (float*)d_out);
}